// round 7
// baseline (speedup 1.0000x reference)
#include <cuda_runtime.h>
#include <math.h>

#define LFRAMES 256
#define IMH 224
#define IMW 224
#define IMC 3
#define NOISE_LEN 766     // 3*L - 2
#define WIN 511           // 2*L - 1
#define ROWF (IMW * IMC)  // 672 floats per image row

// Per-frame source matrices, padded to 12 floats (3 x float4) per frame.
__device__ float g_M[LFRAMES * 12];

// log2(1.1)
#define LOG2_BASE 0.13750352374993496f

// ---------------------------------------------------------------------------
// Kernel 1: smoothing + matrix build (~3 us).
// ---------------------------------------------------------------------------
__global__ void __launch_bounds__(128)
smooth_matrices_kernel(const float* __restrict__ noise,
                       const float* __restrict__ basis) {
    __shared__ float wn[WIN];
    __shared__ float red[4][4];

    const int tid = threadIdx.x;
    const int t = blockIdx.x;

    const float p255 = exp2f(255.f * LOG2_BASE);
    const float wsum = (p255 - 1.f) * 10.f + (p255 * 1.1f - 1.f) * 10.f;
    const float inv = 1.f / wsum;

    for (int j = tid; j < WIN; j += 128) {
        int e = (j < 255) ? j : (510 - j);
        wn[j] = exp2f((float)e * LOG2_BASE) * inv;
    }
    __syncthreads();

    float part[4] = {0.f, 0.f, 0.f, 0.f};
    #pragma unroll
    for (int r = 0; r < 4; r++) {
        const float* nr = noise + r * NOISE_LEN + t;
        float acc = 0.f;
        #pragma unroll 4
        for (int k = tid; k < WIN; k += 128) {
            acc = fmaf(__ldg(nr + k), wn[k], acc);
        }
        part[r] = acc;
    }
    const int lane = tid & 31;
    const int wrp = tid >> 5;
    #pragma unroll
    for (int r = 0; r < 4; r++) {
        float v = part[r];
        #pragma unroll
        for (int off = 16; off > 0; off >>= 1)
            v += __shfl_down_sync(0xFFFFFFFFu, v, off);
        if (lane == 0) red[wrp][r] = v;
    }
    __syncthreads();

    if (tid == 0) {
        float wv[4];
        float sum_wv = 0.f;
        #pragma unroll
        for (int r = 0; r < 4; r++) {
            float v = (red[0][r] + red[1][r]) + (red[2][r] + red[3][r]);
            v = fmaxf(v, 0.f);
            wv[r] = v;
            sum_wv += v;
        }
        float W9[9];
        const float rem = 4.f - sum_wv;
        #pragma unroll
        for (int i = 0; i < 9; i++) {
            float e = 0.f;
            #pragma unroll
            for (int r = 0; r < 4; r++)
                e = fmaf(wv[r], __ldg(basis + r * 9 + i), e);
            if (i == 0 || i == 4 || i == 8) e += rem;
            W9[i] = e;
        }
        const float s = 1.f / 223.f;
        float T[9];
        #pragma unroll
        for (int i = 0; i < 3; i++) {
            T[i * 3 + 0] = W9[i * 3 + 0] * s;
            T[i * 3 + 1] = W9[i * 3 + 1] * s;
            T[i * 3 + 2] = -0.5f * W9[i * 3 + 0] - 0.5f * W9[i * 3 + 1] + W9[i * 3 + 2];
        }
        float Mm[9];
        #pragma unroll
        for (int j = 0; j < 3; j++) {
            Mm[0 * 3 + j] = 223.f * T[0 * 3 + j] + 111.5f * T[2 * 3 + j];
            Mm[1 * 3 + j] = 223.f * T[1 * 3 + j] + 111.5f * T[2 * 3 + j];
            Mm[2 * 3 + j] = T[2 * 3 + j];
        }
        #pragma unroll
        for (int i = 0; i < 9; i++)
            g_M[t * 12 + i] = Mm[i];
        g_M[t * 12 + 9]  = 0.f;
        g_M[t * 12 + 10] = 0.f;
        g_M[t * 12 + 11] = 0.f;
    }
}

// ---------------------------------------------------------------------------
// Extract the two 3-float corner pixels from a 9-float aligned window.
// ---------------------------------------------------------------------------
__device__ __forceinline__ void extract2px(const float4 A, const float4 Bv, float C,
                                           bool t2, bool t1, bool pos0, bool pos1,
                                           float3& p0, float3& p1) {
    const float u0 = t2 ? A.z  : A.x;
    const float u1 = t2 ? A.w  : A.y;
    const float u2 = t2 ? Bv.x : A.z;
    const float u3 = t2 ? Bv.y : A.w;
    const float u4 = t2 ? Bv.z : Bv.x;
    const float u5 = t2 ? Bv.w : Bv.y;
    const float u6 = t2 ? C    : Bv.z;

    const float s0 = t1 ? u1 : u0;
    const float s1 = t1 ? u2 : u1;
    const float s2 = t1 ? u3 : u2;
    const float s3 = t1 ? u4 : u3;
    const float s4 = t1 ? u5 : u4;
    const float s5 = t1 ? u6 : u5;

    p0.x = pos0 ? s3 : s0;  p0.y = pos0 ? s4 : s1;  p0.z = pos0 ? s5 : s2;
    p1.x = pos1 ? s3 : s0;  p1.y = pos1 ? s4 : s1;  p1.z = pos1 ? s5 : s2;
}

// ---------------------------------------------------------------------------
// Kernel 2: projective bilinear warp. 1 px/thread, consecutive lanes (R4
// gather). Output repacked across the warp with SHFL (no L1 traffic) so
// lanes 0-23 each store one contiguous STG.128: 3 store wavefronts/warp.
// grid (224, 256), block 224 (7 warps).
// ---------------------------------------------------------------------------
__global__ void __launch_bounds__(224)
warp_kernel(const float* __restrict__ x, float* __restrict__ out) {
    const int px = threadIdx.x;     // 0..223
    const int py = blockIdx.x;      // 0..223
    const int l  = blockIdx.y;      // 0..255
    const int w    = px >> 5;
    const int lane = px & 31;

    const float4* Mp = (const float4*)(g_M + l * 12);
    const float4 m0 = __ldg(Mp + 0);
    const float4 m1 = __ldg(Mp + 1);
    const float4 m2 = __ldg(Mp + 2);
    const float M0 = m0.x, M1 = m0.y, M2 = m0.z, M3 = m0.w;
    const float M4 = m1.x, M5 = m1.y, M6 = m1.z, M7 = m1.w;
    const float M8 = m2.x;

    const float fx = (float)px, fy = (float)py;

    const float den = fmaf(M6, fx, fmaf(M7, fy, M8));
    const float rden = __frcp_rn(den);
    const float sx = fmaf(M0, fx, fmaf(M1, fy, M2)) * rden;
    const float sy = fmaf(M3, fx, fmaf(M4, fy, M5)) * rden;

    const float x0f = floorf(sx);
    const float y0f = floorf(sy);
    const float wx = sx - x0f;
    const float wy = sy - y0f;

    const float W1 = (float)(IMW - 1), H1 = (float)(IMH - 1);

    const bool vx0 = (x0f >= 0.f) && (x0f <= W1);
    const bool vx1 = (x0f >= -1.f) && (x0f <= W1 - 1.f);
    const float y1f = y0f + 1.f;
    const bool vy0 = (y0f >= 0.f) && (y0f <= H1);
    const bool vy1 = (y1f >= 0.f) && (y1f <= H1);
    const int yi0 = (int)fminf(fmaxf(y0f, 0.f), H1);
    const int yi1 = (int)fminf(fmaxf(y1f, 0.f), H1);

    const float w00 = (vy0 && vx0) ? (1.f - wy) * (1.f - wx) : 0.f;
    const float w01 = (vy0 && vx1) ? (1.f - wy) * wx         : 0.f;
    const float w10 = (vy1 && vx0) ? wy * (1.f - wx)         : 0.f;
    const float w11 = (vy1 && vx1) ? wy * wx                 : 0.f;

    const float basef = fminf(fmaxf(x0f, 0.f), 222.f);
    const int base = (int)basef;
    const int fi = base * 3;
    const int s  = fi & 3;
    const int fa = fi & ~3;
    const bool t2 = (s & 2) != 0;
    const bool t1 = (s & 1) != 0;
    const bool pos0 = (x0f > 222.5f);
    const bool pos1 = (x0f > -0.5f);
    const bool needC = (s == 3);

    const float* img  = x + (size_t)l * (IMH * ROWF);
    const float* row0 = img + yi0 * ROWF;
    const float* row1 = img + yi1 * ROWF;

    const float4 A0 = __ldg((const float4*)(row0 + fa));
    const float4 B0 = __ldg((const float4*)(row0 + fa + 4));
    const float4 A1 = __ldg((const float4*)(row1 + fa));
    const float4 B1 = __ldg((const float4*)(row1 + fa + 4));
    const float C0 = needC ? __ldg(row0 + fa + 8) : 0.f;
    const float C1 = needC ? __ldg(row1 + fa + 8) : 0.f;

    float3 p00, p01, p10, p11;
    extract2px(A0, B0, C0, t2, t1, pos0, pos1, p00, p01);
    extract2px(A1, B1, C1, t2, t1, pos0, pos1, p10, p11);

    float a0 = p00.x * w00, a1 = p00.y * w00, a2 = p00.z * w00;
    a0 = fmaf(p01.x, w01, a0); a1 = fmaf(p01.y, w01, a1); a2 = fmaf(p01.z, w01, a2);
    a0 = fmaf(p10.x, w10, a0); a1 = fmaf(p10.y, w10, a1); a2 = fmaf(p10.z, w10, a2);
    a0 = fmaf(p11.x, w11, a0); a1 = fmaf(p11.y, w11, a1); a2 = fmaf(p11.z, w11, a2);

    // Warp repack via SHFL: lane j<24 assembles output floats [4j, 4j+4)
    // (warp covers 96 floats = 32 px * 3 ch) and stores one float4.
    const int idx = 4 * lane;
    const int srcA = min(idx / 3, 31);
    const int srcB = min(srcA + 1, 31);
    const int r = idx - srcA * 3;   // idx % 3 for lane<24

    const unsigned FULL = 0xFFFFFFFFu;
    const float A0s = __shfl_sync(FULL, a0, srcA);
    const float A1s = __shfl_sync(FULL, a1, srcA);
    const float A2s = __shfl_sync(FULL, a2, srcA);
    const float B0s = __shfl_sync(FULL, a0, srcB);
    const float B1s = __shfl_sync(FULL, a1, srcB);
    const float B2s = __shfl_sync(FULL, a2, srcB);

    float4 V;
    V.x = (r == 0) ? A0s : ((r == 1) ? A1s : A2s);
    V.y = (r == 0) ? A1s : ((r == 1) ? A2s : B0s);
    V.z = (r == 0) ? A2s : ((r == 1) ? B0s : B1s);
    V.w = (r == 0) ? B0s : ((r == 1) ? B1s : B2s);

    if (lane < 24) {
        float4* o = (float4*)(out + (size_t)(l * IMH + py) * ROWF + w * 96);
        o[lane] = V;
    }
}

extern "C" void kernel_launch(void* const* d_in, const int* in_sizes, int n_in,
                              void* d_out, int out_size) {
    const float* x     = (const float*)d_in[0];   // (8,32,224,224,3)
    const float* noise = (const float*)d_in[1];   // (4, 766)
    const float* basis = (const float*)d_in[2];   // (4, 3, 3)
    float* out = (float*)d_out;

    smooth_matrices_kernel<<<LFRAMES, 128>>>(noise, basis);
    warp_kernel<<<dim3(IMH, LFRAMES), IMW>>>(x, out);
}

// round 8
// speedup vs baseline: 1.1472x; 1.1472x over previous
#include <cuda_runtime.h>
#include <math.h>

#define LFRAMES 256
#define IMH 224
#define IMW 224
#define IMC 3
#define NOISE_LEN 766     // 3*L - 2
#define WIN 511           // 2*L - 1
#define ROWF (IMW * IMC)  // 672 floats per image row

// Per-frame source matrices, padded to 12 floats (3 x float4) per frame.
__device__ float g_M[LFRAMES * 12];

// log2(1.1)
#define LOG2_BASE 0.13750352374993496f

// ---------------------------------------------------------------------------
// Kernel 1: smoothing + matrix build (~3 us).
// ---------------------------------------------------------------------------
__global__ void __launch_bounds__(128)
smooth_matrices_kernel(const float* __restrict__ noise,
                       const float* __restrict__ basis) {
    __shared__ float wn[WIN];
    __shared__ float red[4][4];

    const int tid = threadIdx.x;
    const int t = blockIdx.x;

    const float p255 = exp2f(255.f * LOG2_BASE);
    const float wsum = (p255 - 1.f) * 10.f + (p255 * 1.1f - 1.f) * 10.f;
    const float inv = 1.f / wsum;

    for (int j = tid; j < WIN; j += 128) {
        int e = (j < 255) ? j : (510 - j);
        wn[j] = exp2f((float)e * LOG2_BASE) * inv;
    }
    __syncthreads();

    float part[4] = {0.f, 0.f, 0.f, 0.f};
    #pragma unroll
    for (int r = 0; r < 4; r++) {
        const float* nr = noise + r * NOISE_LEN + t;
        float acc = 0.f;
        #pragma unroll 4
        for (int k = tid; k < WIN; k += 128) {
            acc = fmaf(__ldg(nr + k), wn[k], acc);
        }
        part[r] = acc;
    }
    const int lane = tid & 31;
    const int wrp = tid >> 5;
    #pragma unroll
    for (int r = 0; r < 4; r++) {
        float v = part[r];
        #pragma unroll
        for (int off = 16; off > 0; off >>= 1)
            v += __shfl_down_sync(0xFFFFFFFFu, v, off);
        if (lane == 0) red[wrp][r] = v;
    }
    __syncthreads();

    if (tid == 0) {
        float wv[4];
        float sum_wv = 0.f;
        #pragma unroll
        for (int r = 0; r < 4; r++) {
            float v = (red[0][r] + red[1][r]) + (red[2][r] + red[3][r]);
            v = fmaxf(v, 0.f);
            wv[r] = v;
            sum_wv += v;
        }
        float W9[9];
        const float rem = 4.f - sum_wv;
        #pragma unroll
        for (int i = 0; i < 9; i++) {
            float e = 0.f;
            #pragma unroll
            for (int r = 0; r < 4; r++)
                e = fmaf(wv[r], __ldg(basis + r * 9 + i), e);
            if (i == 0 || i == 4 || i == 8) e += rem;
            W9[i] = e;
        }
        const float s = 1.f / 223.f;
        float T[9];
        #pragma unroll
        for (int i = 0; i < 3; i++) {
            T[i * 3 + 0] = W9[i * 3 + 0] * s;
            T[i * 3 + 1] = W9[i * 3 + 1] * s;
            T[i * 3 + 2] = -0.5f * W9[i * 3 + 0] - 0.5f * W9[i * 3 + 1] + W9[i * 3 + 2];
        }
        float Mm[9];
        #pragma unroll
        for (int j = 0; j < 3; j++) {
            Mm[0 * 3 + j] = 223.f * T[0 * 3 + j] + 111.5f * T[2 * 3 + j];
            Mm[1 * 3 + j] = 223.f * T[1 * 3 + j] + 111.5f * T[2 * 3 + j];
            Mm[2 * 3 + j] = T[2 * 3 + j];
        }
        #pragma unroll
        for (int i = 0; i < 9; i++)
            g_M[t * 12 + i] = Mm[i];
        g_M[t * 12 + 9]  = 0.f;
        g_M[t * 12 + 10] = 0.f;
        g_M[t * 12 + 11] = 0.f;
    }
}

// ---------------------------------------------------------------------------
// Interior extraction: span = vflat[s .. s+5], s = 2*t2 + t1;
// p0 = span[0..2], p1 = span[3..5]. 13 SELs.
// ---------------------------------------------------------------------------
__device__ __forceinline__ void extract6(const float4 A, const float4 Bv, float C,
                                         bool t2, bool t1,
                                         float3& p0, float3& p1) {
    const float u0 = t2 ? A.z  : A.x;
    const float u1 = t2 ? A.w  : A.y;
    const float u2 = t2 ? Bv.x : A.z;
    const float u3 = t2 ? Bv.y : A.w;
    const float u4 = t2 ? Bv.z : Bv.x;
    const float u5 = t2 ? Bv.w : Bv.y;
    const float u6 = t2 ? C    : Bv.z;

    p0.x = t1 ? u1 : u0;
    p0.y = t1 ? u2 : u1;
    p0.z = t1 ? u3 : u2;
    p1.x = t1 ? u4 : u3;
    p1.y = t1 ? u5 : u4;
    p1.z = t1 ? u6 : u5;
}

// Full (border-capable) extraction with corner position selects.
__device__ __forceinline__ void extract2px(const float4 A, const float4 Bv, float C,
                                           bool t2, bool t1, bool pos0, bool pos1,
                                           float3& p0, float3& p1) {
    const float u0 = t2 ? A.z  : A.x;
    const float u1 = t2 ? A.w  : A.y;
    const float u2 = t2 ? Bv.x : A.z;
    const float u3 = t2 ? Bv.y : A.w;
    const float u4 = t2 ? Bv.z : Bv.x;
    const float u5 = t2 ? Bv.w : Bv.y;
    const float u6 = t2 ? C    : Bv.z;

    const float s0 = t1 ? u1 : u0;
    const float s1 = t1 ? u2 : u1;
    const float s2 = t1 ? u3 : u2;
    const float s3 = t1 ? u4 : u3;
    const float s4 = t1 ? u5 : u4;
    const float s5 = t1 ? u6 : u5;

    p0.x = pos0 ? s3 : s0;  p0.y = pos0 ? s4 : s1;  p0.z = pos0 ? s5 : s2;
    p1.x = pos1 ? s3 : s0;  p1.y = pos1 ? s4 : s1;  p1.z = pos1 ? s5 : s2;
}

// ---------------------------------------------------------------------------
// Kernel 2: projective bilinear warp. 1 px/thread, consecutive lanes.
// Warp-uniform fast path for interior warps (no validity/clamp logic),
// full R4 body only for boundary warps. grid (224, 256), block 224.
// ---------------------------------------------------------------------------
__global__ void __launch_bounds__(224)
warp_kernel(const float* __restrict__ x, float* __restrict__ out) {
    const int px = threadIdx.x;     // 0..223
    const int py = blockIdx.x;      // 0..223
    const int l  = blockIdx.y;      // 0..255

    const float4* Mp = (const float4*)(g_M + l * 12);
    const float4 m0 = __ldg(Mp + 0);
    const float4 m1 = __ldg(Mp + 1);
    const float4 m2 = __ldg(Mp + 2);
    const float M0 = m0.x, M1 = m0.y, M2 = m0.z, M3 = m0.w;
    const float M4 = m1.x, M5 = m1.y, M6 = m1.z, M7 = m1.w;
    const float M8 = m2.x;

    const float fx = (float)px, fy = (float)py;

    const float den = fmaf(M6, fx, fmaf(M7, fy, M8));
    const float rden = __frcp_rn(den);
    const float sx = fmaf(M0, fx, fmaf(M1, fy, M2)) * rden;
    const float sy = fmaf(M3, fx, fmaf(M4, fy, M5)) * rden;

    const float x0f = floorf(sx);
    const float y0f = floorf(sy);
    const float wx = sx - x0f;
    const float wy = sy - y0f;

    const float* img = x + (size_t)l * (IMH * ROWF);

    float a0, a1, a2;

    const bool interior = (x0f >= 0.f) && (x0f <= 222.f) &&
                          (y0f >= 0.f) && (y0f <= 222.f);

    if (__all_sync(0xFFFFFFFFu, interior)) {
        // ---------------- fast path: fully interior warp ----------------
        const int yi0 = (int)y0f;
        const float* row0 = img + yi0 * ROWF;
        const float* row1 = row0 + ROWF;

        const int fi = (int)x0f * 3;
        const int s  = fi & 3;
        const int fa = fi & ~3;
        const bool t2 = (s & 2) != 0;
        const bool t1 = (s & 1) != 0;
        const bool needC = (s == 3);

        const float4 A0 = __ldg((const float4*)(row0 + fa));
        const float4 B0 = __ldg((const float4*)(row0 + fa + 4));
        const float4 A1 = __ldg((const float4*)(row1 + fa));
        const float4 B1 = __ldg((const float4*)(row1 + fa + 4));
        const float C0 = needC ? __ldg(row0 + fa + 8) : 0.f;
        const float C1 = needC ? __ldg(row1 + fa + 8) : 0.f;

        float3 p00, p01, p10, p11;
        extract6(A0, B0, C0, t2, t1, p00, p01);
        extract6(A1, B1, C1, t2, t1, p10, p11);

        const float w00 = (1.f - wy) * (1.f - wx);
        const float w01 = (1.f - wy) * wx;
        const float w10 = wy * (1.f - wx);
        const float w11 = wy * wx;

        a0 = p00.x * w00; a1 = p00.y * w00; a2 = p00.z * w00;
        a0 = fmaf(p01.x, w01, a0); a1 = fmaf(p01.y, w01, a1); a2 = fmaf(p01.z, w01, a2);
        a0 = fmaf(p10.x, w10, a0); a1 = fmaf(p10.y, w10, a1); a2 = fmaf(p10.z, w10, a2);
        a0 = fmaf(p11.x, w11, a0); a1 = fmaf(p11.y, w11, a1); a2 = fmaf(p11.z, w11, a2);
    } else {
        // ---------------- slow path: border-capable (R4 body) ----------------
        const float W1 = (float)(IMW - 1), H1 = (float)(IMH - 1);

        const bool vx0 = (x0f >= 0.f) && (x0f <= W1);
        const bool vx1 = (x0f >= -1.f) && (x0f <= W1 - 1.f);
        const float y1f = y0f + 1.f;
        const bool vy0 = (y0f >= 0.f) && (y0f <= H1);
        const bool vy1 = (y1f >= 0.f) && (y1f <= H1);
        const int yi0 = (int)fminf(fmaxf(y0f, 0.f), H1);
        const int yi1 = (int)fminf(fmaxf(y1f, 0.f), H1);

        const float w00 = (vy0 && vx0) ? (1.f - wy) * (1.f - wx) : 0.f;
        const float w01 = (vy0 && vx1) ? (1.f - wy) * wx         : 0.f;
        const float w10 = (vy1 && vx0) ? wy * (1.f - wx)         : 0.f;
        const float w11 = (vy1 && vx1) ? wy * wx                 : 0.f;

        const float basef = fminf(fmaxf(x0f, 0.f), 222.f);
        const int base = (int)basef;
        const int fi = base * 3;
        const int s  = fi & 3;
        const int fa = fi & ~3;
        const bool t2 = (s & 2) != 0;
        const bool t1 = (s & 1) != 0;
        const bool pos0 = (x0f > 222.5f);
        const bool pos1 = (x0f > -0.5f);
        const bool needC = (s == 3);

        const float* row0 = img + yi0 * ROWF;
        const float* row1 = img + yi1 * ROWF;

        const float4 A0 = __ldg((const float4*)(row0 + fa));
        const float4 B0 = __ldg((const float4*)(row0 + fa + 4));
        const float4 A1 = __ldg((const float4*)(row1 + fa));
        const float4 B1 = __ldg((const float4*)(row1 + fa + 4));
        const float C0 = needC ? __ldg(row0 + fa + 8) : 0.f;
        const float C1 = needC ? __ldg(row1 + fa + 8) : 0.f;

        float3 p00, p01, p10, p11;
        extract2px(A0, B0, C0, t2, t1, pos0, pos1, p00, p01);
        extract2px(A1, B1, C1, t2, t1, pos0, pos1, p10, p11);

        a0 = p00.x * w00; a1 = p00.y * w00; a2 = p00.z * w00;
        a0 = fmaf(p01.x, w01, a0); a1 = fmaf(p01.y, w01, a1); a2 = fmaf(p01.z, w01, a2);
        a0 = fmaf(p10.x, w10, a0); a1 = fmaf(p10.y, w10, a1); a2 = fmaf(p10.z, w10, a2);
        a0 = fmaf(p11.x, w11, a0); a1 = fmaf(p11.y, w11, a1); a2 = fmaf(p11.z, w11, a2);
    }

    float* o = out + (size_t)(l * IMH + py) * ROWF + px * 3;
    o[0] = a0;
    o[1] = a1;
    o[2] = a2;
}

extern "C" void kernel_launch(void* const* d_in, const int* in_sizes, int n_in,
                              void* d_out, int out_size) {
    const float* x     = (const float*)d_in[0];   // (8,32,224,224,3)
    const float* noise = (const float*)d_in[1];   // (4, 766)
    const float* basis = (const float*)d_in[2];   // (4, 3, 3)
    float* out = (float*)d_out;

    smooth_matrices_kernel<<<LFRAMES, 128>>>(noise, basis);
    warp_kernel<<<dim3(IMH, LFRAMES), IMW>>>(x, out);
}